// round 11
// baseline (speedup 1.0000x reference)
#include <cuda_runtime.h>
#include <cstdint>

#define HPAD   66
#define CIN    128
#define OC     128
#define HW     4096
#define NB     4
#define NS     9
#define NCHUNK 36
#define STAGES 6

// ---- device scratch ----
__device__ float  g_xpad[NB * HPAD * HPAD * CIN + 64];  // NHWC padded x
__device__ float  g_wk2[NS * OC * CIN];                 // [n][oc][c], tf32-rounded
__device__ float4 g_gw[NB * NS * HW];                   // bilinear weights
__device__ int4   g_gi[NB * NS * HW];                   // gather indices (66x66 plane)

// ---- dynamic smem layout (bytes) ----
#define SM_TPTR   0
#define SM_EMPTY(s) (16 + 8 * (s))
#define SM_A(s)   (1024 + (s) * 32768)
#define SM_B(s)   (SM_A(s) + 16384)
#define SM_TS     1024               /* aliases ring stage 0: free when epilogue runs */
#define SM_TOTAL  (1024 + STAGES * 32768)

#define TMEM_COLS 128
// idesc kind::tf32: dtype=F32(1)<<4, atype=TF32(2)<<7, btype=TF32(2)<<10,
// N>>3 (16)<<17, M>>4 (8)<<24
#define IDESC 0x8200910u

#define SW128(o) ((o) ^ (((o) >> 3) & 0x70))

// Feature gate: tcgen05 only exists in the compute_103a device pass.
#if !defined(__CUDA_ARCH__) || defined(__CUDA_ARCH_FEAT_SM103_ALL)
#define HAS_TCGEN05 1
#else
#define HAS_TCGEN05 0
#endif

// ---------------- PTX helpers ----------------
__device__ __forceinline__ uint32_t smem_u32(const void* p) {
    uint32_t a;
    asm("{ .reg .u64 t; cvta.to.shared.u64 t, %1; cvt.u32.u64 %0, t; }" : "=r"(a) : "l"(p));
    return a;
}
__device__ __forceinline__ float ftf32(float x) {
    uint32_t r; asm("cvt.rna.tf32.f32 %0, %1;" : "=r"(r) : "f"(x));
    return __uint_as_float(r);
}
__device__ __forceinline__ uint64_t mkdesc(uint32_t addr) {
    const uint64_t base = (2ull << 61) | (1ull << 46) | (64ull << 32) | (1ull << 16);
    return base | ((uint64_t)(addr >> 4) & 0x3FFF);
}
__device__ __forceinline__ void mbar_init(uint32_t a, uint32_t cnt) {
    asm volatile("mbarrier.init.shared.b64 [%0], %1;" :: "r"(a), "r"(cnt) : "memory");
}
__device__ __forceinline__ void mbar_wait(uint32_t a, uint32_t par) {
    uint32_t done;
    asm volatile(
        "{\n\t.reg .pred p;\n\t"
        "mbarrier.try_wait.parity.acquire.cta.shared::cta.b64 p, [%1], %2;\n\t"
        "selp.b32 %0, 1, 0, p;\n\t}"
        : "=r"(done) : "r"(a), "r"(par) : "memory");
    if (!done) {
        asm volatile(
            "{\n\t.reg .pred P1;\n\t"
            "W%=:\n\t"
            "mbarrier.try_wait.parity.acquire.cta.shared::cta.b64 P1, [%0], %1, 0x989680;\n\t"
            "@P1 bra.uni D%=;\n\t"
            "bra.uni W%=;\n\t"
            "D%=:\n\t}"
            :: "r"(a), "r"(par) : "memory");
    }
}
__device__ __forceinline__ void nbar_arrive(int id, int cnt) {
    asm volatile("bar.arrive %0, %1;" :: "r"(id), "r"(cnt) : "memory");
}
__device__ __forceinline__ void nbar_sync(int id, int cnt) {
    asm volatile("bar.sync %0, %1;" :: "r"(id), "r"(cnt) : "memory");
}

#if HAS_TCGEN05
__device__ __forceinline__ void mma_tf32(uint32_t d, uint64_t ad, uint64_t bd, bool acc) {
    uint32_t e = acc ? 1u : 0u, z = 0u;
    asm volatile(
        "{\n\t.reg .pred p;\n\tsetp.ne.u32 p, %5, 0;\n\t"
        "tcgen05.mma.cta_group::1.kind::tf32 [%0], %1, %2, %3, {%4,%4,%4,%4}, p;\n\t}"
        :: "r"(d), "l"(ad), "l"(bd), "r"(IDESC), "r"(z), "r"(e) : "memory");
}
__device__ __forceinline__ void mma_commit(uint32_t mbar) {
    asm volatile(
        "tcgen05.commit.cta_group::1.mbarrier::arrive::one.shared::cluster.b64 [%0];"
        :: "r"(mbar) : "memory");
}
__device__ __forceinline__ void ldtm32(uint32_t* r, uint32_t ta) {
    asm volatile(
        "tcgen05.ld.sync.aligned.32x32b.x32.b32 "
        "{%0,%1,%2,%3,%4,%5,%6,%7,%8,%9,%10,%11,%12,%13,%14,%15,"
        "%16,%17,%18,%19,%20,%21,%22,%23,%24,%25,%26,%27,%28,%29,%30,%31}, [%32];"
        : "=r"(r[0]),"=r"(r[1]),"=r"(r[2]),"=r"(r[3]),"=r"(r[4]),"=r"(r[5]),"=r"(r[6]),"=r"(r[7]),
          "=r"(r[8]),"=r"(r[9]),"=r"(r[10]),"=r"(r[11]),"=r"(r[12]),"=r"(r[13]),"=r"(r[14]),"=r"(r[15]),
          "=r"(r[16]),"=r"(r[17]),"=r"(r[18]),"=r"(r[19]),"=r"(r[20]),"=r"(r[21]),"=r"(r[22]),"=r"(r[23]),
          "=r"(r[24]),"=r"(r[25]),"=r"(r[26]),"=r"(r[27]),"=r"(r[28]),"=r"(r[29]),"=r"(r[30]),"=r"(r[31])
        : "r"(ta));
}
#endif

// ---------------- fused prep: pad/transpose (blocks 0..527) + wk/coef (blocks 528..1103) ---
__global__ __launch_bounds__(256) void prep_kernel(const float* __restrict__ x,
                                                   const float* __restrict__ w,
                                                   const float* __restrict__ off) {
    __shared__ float ts[64 * 65];
    int bk  = blockIdx.x;
    int tid = threadIdx.x;
    if (bk < 528) {
        int half = bk & 1, ri = bk >> 1;
        int hp = ri % HPAD, b = ri / HPAD;
        bool irow = (hp >= 1 && hp <= 64);
        if (irow) {
            const float* xr = x + ((size_t)(b * CIN + half * 64)) * 4096 + (size_t)(hp - 1) * 64;
            #pragma unroll
            for (int i = 0; i < 16; i++) {
                int idx = tid + i * 256;
                int c = idx >> 6, wp = idx & 63;
                ts[c * 65 + wp] = xr[(size_t)c * 4096 + wp];
            }
        }
        __syncthreads();
        float* orow = g_xpad + ((size_t)(b * HPAD + hp)) * HPAD * CIN + half * 64;
        #pragma unroll
        for (int i = 0; i < 5; i++) {
            int idx = tid + i * 256;            // over 66*16 = 1056 float4
            if (idx >= 1056) break;
            int wp = idx >> 4, c4i = idx & 15;
            float4 v = make_float4(0.f, 0.f, 0.f, 0.f);
            if (irow && wp >= 1 && wp <= 64) {
                int c = c4i * 4, wq = wp - 1;
                v = make_float4(ts[c * 65 + wq], ts[(c + 1) * 65 + wq],
                                ts[(c + 2) * 65 + wq], ts[(c + 3) * 65 + wq]);
            }
            *(float4*)(orow + (size_t)wp * CIN + c4i * 4) = v;
        }
    } else {
        int t = (bk - 528) * 256 + tid;
        {   // weight: [n][oc][c] <- w[oc][c][n]
            int c  = t & 127;
            int oc = (t >> 7) & 127;
            int n  = t >> 14;
            g_wk2[(n * OC + oc) * CIN + c] = ftf32(w[(oc * CIN + c) * 9 + n]);
        }
        {   // coefs
            int pix = t & 4095;
            int n   = (t >> 12) % 9;
            int b   = t / (9 * 4096);
            int i   = pix >> 6, j = pix & 63;
            float ox = off[(b * 18 + 2 * n)     * HW + pix];
            float oy = off[(b * 18 + 2 * n + 1) * HW + pix];
            float px = (float)(i + n / 3) + ox;
            float py = (float)(j + n % 3) + oy;
            float fx = floorf(px), fy = floorf(py);
            int qltx = min(max((int)fx, 0), 65);
            int qlty = min(max((int)fy, 0), 65);
            int qrbx = min(max((int)fx + 1, 0), 65);
            int qrby = min(max((int)fy + 1, 0), 65);
            if (px < 1.f || px > 64.f) px = fx;
            if (py < 1.f || py > 64.f) py = fy;
            px = fminf(fmaxf(px, 0.f), 65.f);
            py = fminf(fmaxf(py, 0.f), 65.f);
            float dltx = 1.f + (float)qltx - px;
            float dlty = 1.f + (float)qlty - py;
            float drbx = 1.f - ((float)qrbx - px);
            float drby = 1.f - ((float)qrby - py);
            g_gw[t] = make_float4(dltx * dlty, drbx * drby, dltx * drby, drbx * dlty);
            g_gi[t] = make_int4(qltx * HPAD + qlty, qrbx * HPAD + qrby,
                                qltx * HPAD + qrby, qrbx * HPAD + qlty);
        }
    }
}

// ------- main: 31 builder warps + 1 MMA warp, 6-stage ring, named-barrier full sync -----
__global__ __launch_bounds__(1024, 1) void main_kernel(float* __restrict__ out) {
#if HAS_TCGEN05
    extern __shared__ char sm[];
    uint32_t smb = smem_u32(sm);
    int tid  = threadIdx.x;
    int wid  = tid >> 5;
    int lane = tid & 31;
    int b       = blockIdx.x >> 5;
    int pixbase = (blockIdx.x & 31) << 7;

    if (wid == 0)
        asm volatile("tcgen05.alloc.cta_group::1.sync.aligned.shared::cta.b32 [%0], %1;"
                     :: "r"(smb + SM_TPTR), "r"((uint32_t)TMEM_COLS) : "memory");
    if (tid == 0) {
        #pragma unroll
        for (int s = 0; s < STAGES; s++) mbar_init(smb + SM_EMPTY(s), 1);
    }
    __syncthreads();

    uint32_t tmem_base;
    asm volatile("ld.shared.b32 %0, [%1];" : "=r"(tmem_base) : "r"(smb + SM_TPTR));

    if (wid == 31) {
        // ---------------- dedicated MMA warp ----------------
        #pragma unroll 1
        for (int j = 0; j < NCHUNK; j++) {
            int s = j % STAGES;
            nbar_sync(1 + s, 1024);              // wait all builders' arrivals for chunk j
            if (lane == 0) {
                uint64_t ad = mkdesc(smb + SM_A(s));
                uint64_t bd = mkdesc(smb + SM_B(s));
                #pragma unroll
                for (int k = 0; k < 4; k++)
                    mma_tf32(tmem_base, ad + 2 * k, bd + 2 * k, (j > 0) || (k > 0));
                mma_commit(smb + SM_EMPTY(s));
            }
        }
    } else {
        // ---------------- 31 builder warps (992 threads) ----------------
        int c4 = tid & 7;                        // 16B channel group
        int p0 = tid >> 3;                       // pixel 0..123
        bool extra = (tid < 32);                 // warp 0 also covers pixels 124..127
        int p1 = 124 + (tid >> 3);               // valid only when extra

        const float* xb = g_xpad + (size_t)b * HPAD * HPAD * CIN;

        #pragma unroll 1
        for (int j = 0; j < NCHUNK; j++) {
            int n = j >> 2, cc = j & 3, s = j % STAGES;
            if (j >= STAGES) mbar_wait(smb + SM_EMPTY(s), (j / STAGES - 1) & 1);

            // ---- A tile via cp.async: thread covers oc=p0 (and p1 if extra) ----
            {
                const float* wkb = g_wk2 + ((size_t)n * OC) * CIN + cc * 32 + c4 * 4;
                uint32_t d0 = smb + SM_A(s) + SW128(p0 * 128 + c4 * 16);
                asm volatile("cp.async.cg.shared.global [%0], [%1], 16;"
                             :: "r"(d0), "l"(wkb + (size_t)p0 * CIN) : "memory");
                if (extra) {
                    uint32_t d1 = smb + SM_A(s) + SW128(p1 * 128 + c4 * 16);
                    asm volatile("cp.async.cg.shared.global [%0], [%1], 16;"
                                 :: "r"(d1), "l"(wkb + (size_t)p1 * CIN) : "memory");
                }
                asm volatile("cp.async.commit_group;" ::: "memory");
            }

            // ---- B tile: bilinear gather, 1 (or 2) pixels ----
            const float4* gwp = g_gw + ((size_t)b * NS + n) * HW + pixbase;
            const int4*   gip = g_gi + ((size_t)b * NS + n) * HW + pixbase;
            const float*  cb  = xb + cc * 32 + c4 * 4;
            char* Bs = sm + SM_B(s);
            {
                float4 w0 = gwp[p0]; int4 i0 = gip[p0];
                float4 v0 = *(const float4*)(cb + (size_t)i0.x * CIN);
                float4 v1 = *(const float4*)(cb + (size_t)i0.y * CIN);
                float4 v2 = *(const float4*)(cb + (size_t)i0.z * CIN);
                float4 v3 = *(const float4*)(cb + (size_t)i0.w * CIN);
                float4 r_;
                r_.x = ftf32(w0.x*v0.x + w0.y*v1.x + w0.z*v2.x + w0.w*v3.x);
                r_.y = ftf32(w0.x*v0.y + w0.y*v1.y + w0.z*v2.y + w0.w*v3.y);
                r_.z = ftf32(w0.x*v0.z + w0.y*v1.z + w0.z*v2.z + w0.w*v3.z);
                r_.w = ftf32(w0.x*v0.w + w0.y*v1.w + w0.z*v2.w + w0.w*v3.w);
                *(float4*)(Bs + SW128(p0 * 128 + c4 * 16)) = r_;
            }
            if (extra) {
                float4 w1 = gwp[p1]; int4 i1 = gip[p1];
                float4 u0 = *(const float4*)(cb + (size_t)i1.x * CIN);
                float4 u1 = *(const float4*)(cb + (size_t)i1.y * CIN);
                float4 u2 = *(const float4*)(cb + (size_t)i1.z * CIN);
                float4 u3 = *(const float4*)(cb + (size_t)i1.w * CIN);
                float4 q_;
                q_.x = ftf32(w1.x*u0.x + w1.y*u1.x + w1.z*u2.x + w1.w*u3.x);
                q_.y = ftf32(w1.x*u0.y + w1.y*u1.y + w1.z*u2.y + w1.w*u3.y);
                q_.z = ftf32(w1.x*u0.z + w1.y*u1.z + w1.z*u2.z + w1.w*u3.z);
                q_.w = ftf32(w1.x*u0.w + w1.y*u1.w + w1.z*u2.w + w1.w*u3.w);
                *(float4*)(Bs + SW128(p1 * 128 + c4 * 16)) = q_;
            }

            asm volatile("cp.async.wait_group 0;" ::: "memory");
            asm volatile("fence.proxy.async.shared::cta;" ::: "memory");
            nbar_arrive(1 + s, 1024);
        }
    }

    // last chunk j=35 -> stage 5; 6th completion of empty[5] -> wait parity (6-1)&1 = 1
    mbar_wait(smb + SM_EMPTY((NCHUNK - 1) % STAGES), (NCHUNK / STAGES - 1) & 1);
    asm volatile("tcgen05.fence::after_thread_sync;" ::: "memory");

    // ---- epilogue: TMEM -> smem transpose -> coalesced STG (Ts aliases ring stage 0) ----
    float* Ts = (float*)(sm + SM_TS);
    for (int cg = 0; cg < 4; cg++) {
        if (wid < 4) {
            uint32_t r[32];
            ldtm32(r, tmem_base + cg * 32);
            asm volatile("tcgen05.wait::ld.sync.aligned;" ::: "memory");
            int oc = wid * 32 + lane;
            #pragma unroll
            for (int c = 0; c < 32; c++) Ts[oc * 33 + c] = __uint_as_float(r[c]);
        }
        __syncthreads();
        {
            int ocr = tid >> 3, q4 = (tid & 7) * 4;
            const float* row = Ts + ocr * 33 + q4;
            float* op = out + ((size_t)(b * OC + ocr)) * HW + pixbase + cg * 32 + q4;
            *(float4*)op = make_float4(row[0], row[1], row[2], row[3]);
        }
        __syncthreads();
    }

    if (wid == 0) {
        asm volatile("tcgen05.relinquish_alloc_permit.cta_group::1.sync.aligned;");
        asm volatile("tcgen05.dealloc.cta_group::1.sync.aligned.b32 %0, %1;"
                     :: "r"(tmem_base), "r"((uint32_t)TMEM_COLS));
    }
#else
    (void)out;   // non-103a PTX pass: dead body; sm_103a cubin selected at runtime
#endif
}

// ---------------- launch ----------------
extern "C" void kernel_launch(void* const* d_in, const int* in_sizes, int n_in,
                              void* d_out, int out_size) {
    const float* x   = (const float*)d_in[0];
    const float* off = (const float*)d_in[1];
    const float* w   = (const float*)d_in[2];
    float* out = (float*)d_out;
    (void)in_sizes; (void)n_in; (void)out_size;

    cudaFuncSetAttribute(main_kernel, cudaFuncAttributeMaxDynamicSharedMemorySize, SM_TOTAL);

    prep_kernel<<<528 + 576, 256>>>(x, w, off);
    main_kernel<<<128, 1024, SM_TOTAL>>>(out);
}